// round 1
// baseline (speedup 1.0000x reference)
#include <cuda_runtime.h>
#include <cuda_bf16.h>
#include <math_constants.h>

// Problem constants
#define BB   2
#define LL   2048
#define SS   2048
#define DIN  512
#define DK   512
#define DV   512
#define DOUT 512
#define HH   8
#define HD   64   // DV / H

#define OUT_ELEMS  ((long)BB * LL * DOUT)                 // 2,097,152
#define PROB_ELEMS ((long)BB * HH * (long)LL * (long)SS)  // 67,108,864

// Scratch (device globals — no runtime allocation allowed)
__device__ float g_q  [BB * LL * DK];
__device__ float g_k  [BB * SS * DK];
__device__ float g_v  [BB * SS * DV];
__device__ float g_cb [BB * HH * SS];
__device__ float g_ctx[BB * LL * DV];
__device__ float g_probs[BB * HH * (long)LL * SS];  // fallback if probs not part of d_out

// ---------------------------------------------------------------------------
// Generic tiled SGEMM: C[M,N] = A[M,K] * W[N,K]^T (+ bias[n])
// BM=BN=128, BK=16, 256 threads, 8x8 per-thread microtile.
// All dims assumed multiples of the tile (true here: M=4096, N=512, K=512).
// ---------------------------------------------------------------------------
template <bool HAS_BIAS>
__global__ void gemm_abT_kernel(const float* __restrict__ A,
                                const float* __restrict__ W,
                                const float* __restrict__ bias,
                                float* __restrict__ C,
                                int M, int N, int K) {
    __shared__ __align__(16) float As[16][128];
    __shared__ __align__(16) float Bs[16][128];

    const int tid = threadIdx.x;
    const int bm  = blockIdx.y * 128;
    const int bn  = blockIdx.x * 128;

    const int lr = tid >> 2;          // 0..63 (row within half-tile)
    const int lk = (tid & 3) * 4;     // 0,4,8,12

    const int tr = (tid >> 4) * 8;    // micro-tile row base
    const int tc = (tid & 15) * 8;    // micro-tile col base

    float acc[8][8];
    #pragma unroll
    for (int i = 0; i < 8; i++)
        #pragma unroll
        for (int j = 0; j < 8; j++) acc[i][j] = 0.0f;

    for (int k0 = 0; k0 < K; k0 += 16) {
        #pragma unroll
        for (int i = 0; i < 2; i++) {
            int r = lr + i * 64;
            float4 a = *(const float4*)(A + (size_t)(bm + r) * K + k0 + lk);
            As[lk + 0][r] = a.x; As[lk + 1][r] = a.y;
            As[lk + 2][r] = a.z; As[lk + 3][r] = a.w;
            float4 w = *(const float4*)(W + (size_t)(bn + r) * K + k0 + lk);
            Bs[lk + 0][r] = w.x; Bs[lk + 1][r] = w.y;
            Bs[lk + 2][r] = w.z; Bs[lk + 3][r] = w.w;
        }
        __syncthreads();

        #pragma unroll
        for (int k = 0; k < 16; k++) {
            float af[8], bf[8];
            #pragma unroll
            for (int i = 0; i < 8; i++) af[i] = As[k][tr + i];
            #pragma unroll
            for (int j = 0; j < 8; j++) bf[j] = Bs[k][tc + j];
            #pragma unroll
            for (int i = 0; i < 8; i++)
                #pragma unroll
                for (int j = 0; j < 8; j++) acc[i][j] += af[i] * bf[j];
        }
        __syncthreads();
    }

    #pragma unroll
    for (int i = 0; i < 8; i++) {
        int m = bm + tr + i;
        #pragma unroll
        for (int j = 0; j < 8; j++) {
            int n = bn + tc + j;
            float c = acc[i][j];
            if (HAS_BIAS) c += bias[n];
            C[(size_t)m * N + n] = c;
        }
    }
}

// ---------------------------------------------------------------------------
// Content bias: cb[b,h,s] = sum_d keys[b,s,d] * Wcb[h,d]
// One block per (b,s); 8 warps, warp h computes head h's dot product.
// ---------------------------------------------------------------------------
__global__ void cb_kernel(const float* __restrict__ keys,
                          const float* __restrict__ Wcb,
                          float* __restrict__ cb) {
    const int bs = blockIdx.x;          // 0 .. B*S-1
    const int b  = bs / SS;
    const int s  = bs % SS;
    __shared__ float krow[DIN];
    const int tid = threadIdx.x;
    for (int i = tid; i < DIN; i += 256) krow[i] = keys[(size_t)bs * DIN + i];
    __syncthreads();

    const int w    = tid >> 5;   // head = warp id (8 warps)
    const int lane = tid & 31;
    float sum = 0.0f;
    #pragma unroll 4
    for (int i = lane; i < DIN; i += 32) sum += krow[i] * Wcb[w * DIN + i];
    #pragma unroll
    for (int o = 16; o > 0; o >>= 1) sum += __shfl_down_sync(0xffffffffu, sum, o);
    if (lane == 0) cb[(size_t)(b * HH + w) * SS + s] = sum;
}

// ---------------------------------------------------------------------------
// Scores: probs_raw[b,h,l,s] = (sum_e q[b,l,e]*mixing[h,e]*k[b,s,e] + cb[b,h,s]) / 8
// Same tiling as gemm_abT; mixing folded into B-tile smem load,
// (+cb)*0.125 folded into the epilogue. grid = (S/128, L/128, B*H).
// ---------------------------------------------------------------------------
__global__ void scores_kernel(const float* __restrict__ q,
                              const float* __restrict__ kmat,
                              const float* __restrict__ mixing,
                              const float* __restrict__ cb,
                              float* __restrict__ probs) {
    __shared__ __align__(16) float As[16][128];
    __shared__ __align__(16) float Bs[16][128];
    __shared__ float mix[DK];

    const int z = blockIdx.z;
    const int b = z / HH;
    const int h = z % HH;
    const float* A  = q    + (size_t)b * LL * DK;
    const float* Bm = kmat + (size_t)b * SS * DK;

    const int tid = threadIdx.x;
    const int bm  = blockIdx.y * 128;   // l tile
    const int bn  = blockIdx.x * 128;   // s tile

    for (int i = tid; i < DK; i += 256) mix[i] = mixing[h * DK + i];
    __syncthreads();

    const int lr = tid >> 2;
    const int lk = (tid & 3) * 4;
    const int tr = (tid >> 4) * 8;
    const int tc = (tid & 15) * 8;

    float acc[8][8];
    #pragma unroll
    for (int i = 0; i < 8; i++)
        #pragma unroll
        for (int j = 0; j < 8; j++) acc[i][j] = 0.0f;

    for (int k0 = 0; k0 < DK; k0 += 16) {
        #pragma unroll
        for (int i = 0; i < 2; i++) {
            int r = lr + i * 64;
            float4 a = *(const float4*)(A + (size_t)(bm + r) * DK + k0 + lk);
            As[lk + 0][r] = a.x; As[lk + 1][r] = a.y;
            As[lk + 2][r] = a.z; As[lk + 3][r] = a.w;
            float4 w = *(const float4*)(Bm + (size_t)(bn + r) * DK + k0 + lk);
            Bs[lk + 0][r] = w.x * mix[k0 + lk + 0];
            Bs[lk + 1][r] = w.y * mix[k0 + lk + 1];
            Bs[lk + 2][r] = w.z * mix[k0 + lk + 2];
            Bs[lk + 3][r] = w.w * mix[k0 + lk + 3];
        }
        __syncthreads();

        #pragma unroll
        for (int k = 0; k < 16; k++) {
            float af[8], bf[8];
            #pragma unroll
            for (int i = 0; i < 8; i++) af[i] = As[k][tr + i];
            #pragma unroll
            for (int j = 0; j < 8; j++) bf[j] = Bs[k][tc + j];
            #pragma unroll
            for (int i = 0; i < 8; i++)
                #pragma unroll
                for (int j = 0; j < 8; j++) acc[i][j] += af[i] * bf[j];
        }
        __syncthreads();
    }

    const size_t rowbase = ((size_t)(b * HH + h) * LL);
    #pragma unroll
    for (int j = 0; j < 8; j++) {
        int s = bn + tc + j;
        float cbv = cb[(size_t)(b * HH + h) * SS + s];
        #pragma unroll
        for (int i = 0; i < 8; i++) {
            int l = bm + tr + i;
            probs[(rowbase + l) * SS + s] = (acc[i][j] + cbv) * 0.125f;
        }
    }
}

// ---------------------------------------------------------------------------
// Row softmax over S=2048, in place. One block (256 thr) per (b,h,l) row.
// ---------------------------------------------------------------------------
__global__ void softmax_kernel(float* __restrict__ probs) {
    float4* p = (float4*)(probs + (size_t)blockIdx.x * SS);
    const int tid = threadIdx.x;
    float4 a = p[tid];
    float4 c = p[tid + 256];

    float mx = fmaxf(fmaxf(fmaxf(a.x, a.y), fmaxf(a.z, a.w)),
                     fmaxf(fmaxf(c.x, c.y), fmaxf(c.z, c.w)));
    __shared__ float red[256];
    red[tid] = mx; __syncthreads();
    #pragma unroll
    for (int s = 128; s > 0; s >>= 1) {
        if (tid < s) red[tid] = fmaxf(red[tid], red[tid + s]);
        __syncthreads();
    }
    mx = red[0];
    __syncthreads();

    a.x = __expf(a.x - mx); a.y = __expf(a.y - mx);
    a.z = __expf(a.z - mx); a.w = __expf(a.w - mx);
    c.x = __expf(c.x - mx); c.y = __expf(c.y - mx);
    c.z = __expf(c.z - mx); c.w = __expf(c.w - mx);
    float sum = (a.x + a.y + a.z + a.w) + (c.x + c.y + c.z + c.w);
    red[tid] = sum; __syncthreads();
    #pragma unroll
    for (int s = 128; s > 0; s >>= 1) {
        if (tid < s) red[tid] += red[tid + s];
        __syncthreads();
    }
    float inv = 1.0f / red[0];

    a.x *= inv; a.y *= inv; a.z *= inv; a.w *= inv;
    c.x *= inv; c.y *= inv; c.z *= inv; c.w *= inv;
    p[tid] = a;
    p[tid + 256] = c;
}

// ---------------------------------------------------------------------------
// ctx[b, l, h*64+j] = sum_s probs[b,h,l,s] * v[b, s, h*64+j]
// per (b,h): C[2048 x 64] = P[2048 x 2048] @ Vh[2048 x 64]
// BM=128, BN=64, BK=32, 256 threads, 8x4 microtile. grid = (1, L/128, B*H).
// ---------------------------------------------------------------------------
__global__ void ctx_kernel(const float* __restrict__ probs,
                           const float* __restrict__ v,
                           float* __restrict__ ctx) {
    __shared__ __align__(16) float Ps[32][128];
    __shared__ __align__(16) float Vs[32][64];

    const int z = blockIdx.z;
    const int b = z / HH;
    const int h = z % HH;
    const float* P = probs + (size_t)(b * HH + h) * LL * SS;
    const int bm = blockIdx.y * 128;

    const int tid = threadIdx.x;
    const int tr  = (tid >> 4) * 8;   // 0..120
    const int tc  = (tid & 15) * 4;   // 0..60

    float acc[8][4];
    #pragma unroll
    for (int i = 0; i < 8; i++)
        #pragma unroll
        for (int j = 0; j < 4; j++) acc[i][j] = 0.0f;

    const int prow = tid >> 3;        // 0..31
    const int pk   = (tid & 7) * 4;   // 0..28
    const int vrow = tid >> 4;        // 0..15
    const int vj   = (tid & 15) * 4;  // 0..60

    for (int k0 = 0; k0 < SS; k0 += 32) {
        #pragma unroll
        for (int i = 0; i < 4; i++) {
            int r = prow + i * 32;
            float4 a = *(const float4*)(P + (size_t)(bm + r) * SS + k0 + pk);
            Ps[pk + 0][r] = a.x; Ps[pk + 1][r] = a.y;
            Ps[pk + 2][r] = a.z; Ps[pk + 3][r] = a.w;
        }
        #pragma unroll
        for (int i = 0; i < 2; i++) {
            int r = vrow + i * 16;
            float4 w = *(const float4*)(v + (size_t)(b * SS + k0 + r) * DV + h * HD + vj);
            *(float4*)&Vs[r][vj] = w;
        }
        __syncthreads();

        #pragma unroll
        for (int k = 0; k < 32; k++) {
            float af[8], bf[4];
            #pragma unroll
            for (int i = 0; i < 8; i++) af[i] = Ps[k][tr + i];
            #pragma unroll
            for (int j = 0; j < 4; j++) bf[j] = Vs[k][tc + j];
            #pragma unroll
            for (int i = 0; i < 8; i++)
                #pragma unroll
                for (int j = 0; j < 4; j++) acc[i][j] += af[i] * bf[j];
        }
        __syncthreads();
    }

    #pragma unroll
    for (int i = 0; i < 8; i++) {
        size_t base = (size_t)(b * LL + bm + tr + i) * DV + h * HD;
        #pragma unroll
        for (int j = 0; j < 4; j++) ctx[base + tc + j] = acc[i][j];
    }
}

// ---------------------------------------------------------------------------
extern "C" void kernel_launch(void* const* d_in, const int* in_sizes, int n_in,
                              void* d_out, int out_size) {
    const float* queries = (const float*)d_in[0];
    const float* keys    = (const float*)d_in[1];
    const float* values  = (const float*)d_in[2];
    // d_in[3] = attn_mask (scalar 0, unused by reference)
    const float* Wq      = (const float*)d_in[4];
    const float* Wk      = (const float*)d_in[5];
    const float* Wv      = (const float*)d_in[6];
    const float* bv      = (const float*)d_in[7];
    const float* Wcb     = (const float*)d_in[8];
    const float* mixing  = (const float*)d_in[9];
    const float* Wd      = (const float*)d_in[10];
    const float* bd      = (const float*)d_in[11];

    float* out = (float*)d_out;

    void *pq, *pk, *pv, *pcb, *pctx, *pprobs;
    cudaGetSymbolAddress(&pq,   g_q);
    cudaGetSymbolAddress(&pk,   g_k);
    cudaGetSymbolAddress(&pv,   g_v);
    cudaGetSymbolAddress(&pcb,  g_cb);
    cudaGetSymbolAddress(&pctx, g_ctx);
    cudaGetSymbolAddress(&pprobs, g_probs);

    // probs goes directly into d_out if the harness checks (out, probs) concatenated
    float* probs;
    if ((long)out_size >= OUT_ELEMS + PROB_ELEMS) probs = out + OUT_ELEMS;
    else                                           probs = (float*)pprobs;

    const int M = BB * LL;  // 4096

    // content bias
    cb_kernel<<<BB * SS, 256>>>(keys, Wcb, (float*)pcb);

    // projections
    dim3 gproj(DOUT / 128, M / 128);
    gemm_abT_kernel<false><<<gproj, 256>>>(queries, Wq, nullptr, (float*)pq, M, DK,  DIN);
    gemm_abT_kernel<false><<<gproj, 256>>>(keys,    Wk, nullptr, (float*)pk, M, DK,  DIN);
    gemm_abT_kernel<true ><<<gproj, 256>>>(values,  Wv, bv,      (float*)pv, M, DV,  DIN);

    // scores (+cb, /8) -> probs buffer (pre-softmax)
    dim3 gsc(SS / 128, LL / 128, BB * HH);
    scores_kernel<<<gsc, 256>>>((const float*)pq, (const float*)pk, mixing,
                                (const float*)pcb, probs);

    // softmax in place
    softmax_kernel<<<BB * HH * LL, 256>>>(probs);

    // ctx = probs @ v (per head)
    dim3 gctx(1, LL / 128, BB * HH);
    ctx_kernel<<<gctx, 256>>>(probs, (const float*)pv, (float*)pctx);

    // out = ctx @ Wd^T + bd
    gemm_abT_kernel<true><<<gproj, 256>>>((const float*)pctx, Wd, bd, out, M, DOUT, DV);
}

// round 4
// speedup vs baseline: 1.9372x; 1.9372x over previous
#include <cuda_runtime.h>
#include <cuda_bf16.h>
#include <cstdint>

// Problem constants
#define BB   2
#define LL   2048
#define SS   2048
#define DIN  512
#define DK   512
#define DV   512
#define DOUT 512
#define HH   8
#define HD   64

#define OUT_ELEMS  ((long)BB * LL * DOUT)
#define PROB_ELEMS ((long)BB * HH * (long)LL * (long)SS)

// Scratch (device globals — no runtime allocation allowed)
__device__ float g_q  [BB * LL * DK];
__device__ float g_k  [BB * SS * DK];
__device__ float g_v  [BB * SS * DV];
__device__ float g_cb [BB * HH * SS];
__device__ float g_ctx[BB * LL * DV];
__device__ float g_probs[BB * HH * (long)LL * SS];

// ---------------------------------------------------------------------------
// tf32 helpers (plain sm_80-class PTX — the harness targets sm_103 WITHOUT
// the 'a' suffix, so tcgen05 is unavailable; mma.sync is the tensor path)
// ---------------------------------------------------------------------------
__device__ __forceinline__ float f2tf32(float v) {
    uint32_t r;
    asm("cvt.rna.tf32.f32 %0, %1;" : "=r"(r) : "f"(v));
    return __uint_as_float(r);
}

__device__ __forceinline__ void mma_tf32(float& c0, float& c1, float& c2, float& c3,
                                         float a0, float a1, float a2, float a3,
                                         float b0, float b1) {
    asm volatile(
        "mma.sync.aligned.m16n8k8.row.col.f32.tf32.tf32.f32 "
        "{%0,%1,%2,%3}, {%4,%5,%6,%7}, {%8,%9}, {%0,%1,%2,%3};"
        : "+f"(c0), "+f"(c1), "+f"(c2), "+f"(c3)
        : "r"(__float_as_uint(a0)), "r"(__float_as_uint(a1)),
          "r"(__float_as_uint(a2)), "r"(__float_as_uint(a3)),
          "r"(__float_as_uint(b0)), "r"(__float_as_uint(b1)));
}

// ---------------------------------------------------------------------------
// Scores via tf32 mma.sync:
// P[b,h,l,s] = (sum_e q[b,l,e]*mix[h,e]*k[b,s,e] + cb[b,h,s]) * 0.125
// CTA tile 128x128, BK=16 double-buffered, 8 warps (2m x 4n), warp 64x32.
// grid = (S/128, L/128, B*H), 256 threads.
// ---------------------------------------------------------------------------
#define SKP 20   // smem row stride in floats (padded 16 -> 20: conflict-free frags)

__global__ __launch_bounds__(256, 2)
void scores_mma_kernel(const float* __restrict__ q,
                       const float* __restrict__ kmat,
                       const float* __restrict__ mixing,
                       const float* __restrict__ cb,
                       float* __restrict__ probs) {
    __shared__ float As[2][128][SKP];
    __shared__ float Bs[2][128][SKP];
    __shared__ float mix_s[DK];
    __shared__ float cb_s[128];

    const int tid  = threadIdx.x;
    const int wid  = tid >> 5;
    const int lane = tid & 31;
    const int warp_m = wid >> 2;   // 0..1
    const int warp_n = wid & 3;    // 0..3

    const int z  = blockIdx.z;
    const int b  = z >> 3;
    const int h  = z & 7;
    const int bm = blockIdx.y * 128;   // l tile
    const int bn = blockIdx.x * 128;   // s tile

    const float* Aq = q    + (size_t)b * LL * DK + (size_t)bm * DK;
    const float* Bk = kmat + (size_t)b * SS * DK + (size_t)bn * DK;

    for (int i = tid; i < DK; i += 256) mix_s[i] = mixing[h * DK + i];
    if (tid < 128) cb_s[tid] = cb[(size_t)(b * HH + h) * SS + bn + tid];
    __syncthreads();

    // per-thread gmem tile slice: 2 float4 each for A and B per 16-wide chunk
    const int gr = tid >> 2;          // row 0..63 (+64 for second)
    const int gc = (tid & 3) * 4;     // k-col 0,4,8,12

    float acc[4][4][4];
    #pragma unroll
    for (int i = 0; i < 4; i++)
        #pragma unroll
        for (int j = 0; j < 4; j++)
            #pragma unroll
            for (int t = 0; t < 4; t++) acc[i][j][t] = 0.0f;

    float4 pa[2], pb[2];

    // prefetch + store chunk 0
    #pragma unroll
    for (int i = 0; i < 2; i++) {
        pa[i] = *(const float4*)(Aq + (size_t)(gr + i * 64) * DK + gc);
        pb[i] = *(const float4*)(Bk + (size_t)(gr + i * 64) * DK + gc);
    }
    #pragma unroll
    for (int i = 0; i < 2; i++) {
        int r = gr + i * 64;
        As[0][r][gc + 0] = f2tf32(pa[i].x);
        As[0][r][gc + 1] = f2tf32(pa[i].y);
        As[0][r][gc + 2] = f2tf32(pa[i].z);
        As[0][r][gc + 3] = f2tf32(pa[i].w);
        Bs[0][r][gc + 0] = f2tf32(pb[i].x * mix_s[gc + 0]);
        Bs[0][r][gc + 1] = f2tf32(pb[i].y * mix_s[gc + 1]);
        Bs[0][r][gc + 2] = f2tf32(pb[i].z * mix_s[gc + 2]);
        Bs[0][r][gc + 3] = f2tf32(pb[i].w * mix_s[gc + 3]);
    }
    __syncthreads();

    const int NC = DK / 16;   // 32 chunks
    for (int c = 0; c < NC; c++) {
        if (c + 1 < NC) {
            int kc = (c + 1) * 16;
            #pragma unroll
            for (int i = 0; i < 2; i++) {
                pa[i] = *(const float4*)(Aq + (size_t)(gr + i * 64) * DK + kc + gc);
                pb[i] = *(const float4*)(Bk + (size_t)(gr + i * 64) * DK + kc + gc);
            }
        }

        const int st = c & 1;
        #pragma unroll
        for (int kk = 0; kk < 2; kk++) {
            const int k0 = kk * 8;
            const int ar = lane >> 2;      // 0..7
            const int ac = lane & 3;       // 0..3
            // A fragments: 4 m-atoms
            float a0[4], a1[4], a2[4], a3[4];
            #pragma unroll
            for (int i = 0; i < 4; i++) {
                int m = warp_m * 64 + i * 16;
                a0[i] = As[st][m + ar    ][k0 + ac    ];
                a1[i] = As[st][m + ar + 8][k0 + ac    ];
                a2[i] = As[st][m + ar    ][k0 + ac + 4];
                a3[i] = As[st][m + ar + 8][k0 + ac + 4];
            }
            // B fragments: 4 n-atoms
            float b0[4], b1[4];
            #pragma unroll
            for (int j = 0; j < 4; j++) {
                int n = warp_n * 32 + j * 8 + (lane >> 2);
                b0[j] = Bs[st][n][k0 + ac    ];
                b1[j] = Bs[st][n][k0 + ac + 4];
            }
            #pragma unroll
            for (int i = 0; i < 4; i++)
                #pragma unroll
                for (int j = 0; j < 4; j++)
                    mma_tf32(acc[i][j][0], acc[i][j][1], acc[i][j][2], acc[i][j][3],
                             a0[i], a1[i], a2[i], a3[i], b0[j], b1[j]);
        }

        if (c + 1 < NC) {
            __syncthreads();
            const int ns = (c + 1) & 1;
            const int kc = (c + 1) * 16;
            #pragma unroll
            for (int i = 0; i < 2; i++) {
                int r = gr + i * 64;
                As[ns][r][gc + 0] = f2tf32(pa[i].x);
                As[ns][r][gc + 1] = f2tf32(pa[i].y);
                As[ns][r][gc + 2] = f2tf32(pa[i].z);
                As[ns][r][gc + 3] = f2tf32(pa[i].w);
                Bs[ns][r][gc + 0] = f2tf32(pb[i].x * mix_s[kc + gc + 0]);
                Bs[ns][r][gc + 1] = f2tf32(pb[i].y * mix_s[kc + gc + 1]);
                Bs[ns][r][gc + 2] = f2tf32(pb[i].z * mix_s[kc + gc + 2]);
                Bs[ns][r][gc + 3] = f2tf32(pb[i].w * mix_s[kc + gc + 3]);
            }
            __syncthreads();
        }
    }

    // Epilogue: (acc + cb) * 0.125, st.v2 (sector-aligned pairs)
    const size_t rowbase = (size_t)(b * HH + h) * LL;
    #pragma unroll
    for (int i = 0; i < 4; i++) {
        int row = bm + warp_m * 64 + i * 16 + (lane >> 2);
        #pragma unroll
        for (int j = 0; j < 4; j++) {
            int col = warp_n * 32 + j * 8 + (lane & 3) * 2;
            float cb0 = cb_s[col], cb1 = cb_s[col + 1];
            float2 v0, v1;
            v0.x = (acc[i][j][0] + cb0) * 0.125f;
            v0.y = (acc[i][j][1] + cb1) * 0.125f;
            v1.x = (acc[i][j][2] + cb0) * 0.125f;
            v1.y = (acc[i][j][3] + cb1) * 0.125f;
            *(float2*)(probs + (rowbase + row    ) * SS + bn + col) = v0;
            *(float2*)(probs + (rowbase + row + 8) * SS + bn + col) = v1;
        }
    }
}

// ---------------------------------------------------------------------------
// SIMT kernels (unchanged): projections, cb, softmax, ctx
// ---------------------------------------------------------------------------
template <bool HAS_BIAS>
__global__ void gemm_abT_kernel(const float* __restrict__ A,
                                const float* __restrict__ W,
                                const float* __restrict__ bias,
                                float* __restrict__ C,
                                int M, int N, int K) {
    __shared__ __align__(16) float As[16][128];
    __shared__ __align__(16) float Bs[16][128];
    const int tid = threadIdx.x;
    const int bm  = blockIdx.y * 128;
    const int bn  = blockIdx.x * 128;
    const int lr = tid >> 2;
    const int lk = (tid & 3) * 4;
    const int tr = (tid >> 4) * 8;
    const int tc = (tid & 15) * 8;

    float acc[8][8];
    #pragma unroll
    for (int i = 0; i < 8; i++)
        #pragma unroll
        for (int j = 0; j < 8; j++) acc[i][j] = 0.0f;

    for (int k0 = 0; k0 < K; k0 += 16) {
        #pragma unroll
        for (int i = 0; i < 2; i++) {
            int r = lr + i * 64;
            float4 a = *(const float4*)(A + (size_t)(bm + r) * K + k0 + lk);
            As[lk + 0][r] = a.x; As[lk + 1][r] = a.y;
            As[lk + 2][r] = a.z; As[lk + 3][r] = a.w;
            float4 w = *(const float4*)(W + (size_t)(bn + r) * K + k0 + lk);
            Bs[lk + 0][r] = w.x; Bs[lk + 1][r] = w.y;
            Bs[lk + 2][r] = w.z; Bs[lk + 3][r] = w.w;
        }
        __syncthreads();
        #pragma unroll
        for (int k = 0; k < 16; k++) {
            float af[8], bf[8];
            #pragma unroll
            for (int i = 0; i < 8; i++) af[i] = As[k][tr + i];
            #pragma unroll
            for (int j = 0; j < 8; j++) bf[j] = Bs[k][tc + j];
            #pragma unroll
            for (int i = 0; i < 8; i++)
                #pragma unroll
                for (int j = 0; j < 8; j++) acc[i][j] += af[i] * bf[j];
        }
        __syncthreads();
    }
    #pragma unroll
    for (int i = 0; i < 8; i++) {
        int m = bm + tr + i;
        #pragma unroll
        for (int j = 0; j < 8; j++) {
            int n = bn + tc + j;
            float c = acc[i][j];
            if (HAS_BIAS) c += bias[n];
            C[(size_t)m * N + n] = c;
        }
    }
}

__global__ void cb_kernel(const float* __restrict__ keys,
                          const float* __restrict__ Wcb,
                          float* __restrict__ cb) {
    const int bs = blockIdx.x;
    const int b  = bs / SS;
    const int s  = bs % SS;
    __shared__ float krow[DIN];
    const int tid = threadIdx.x;
    for (int i = tid; i < DIN; i += 256) krow[i] = keys[(size_t)bs * DIN + i];
    __syncthreads();
    const int w    = tid >> 5;
    const int lane = tid & 31;
    float sum = 0.0f;
    #pragma unroll 4
    for (int i = lane; i < DIN; i += 32) sum += krow[i] * Wcb[w * DIN + i];
    #pragma unroll
    for (int o = 16; o > 0; o >>= 1) sum += __shfl_down_sync(0xffffffffu, sum, o);
    if (lane == 0) cb[(size_t)(b * HH + w) * SS + s] = sum;
}

__global__ void softmax_kernel(float* __restrict__ probs) {
    float4* p = (float4*)(probs + (size_t)blockIdx.x * SS);
    const int tid = threadIdx.x;
    float4 a = p[tid];
    float4 c = p[tid + 256];
    float mx = fmaxf(fmaxf(fmaxf(a.x, a.y), fmaxf(a.z, a.w)),
                     fmaxf(fmaxf(c.x, c.y), fmaxf(c.z, c.w)));
    __shared__ float red[256];
    red[tid] = mx; __syncthreads();
    #pragma unroll
    for (int s = 128; s > 0; s >>= 1) {
        if (tid < s) red[tid] = fmaxf(red[tid], red[tid + s]);
        __syncthreads();
    }
    mx = red[0];
    __syncthreads();
    a.x = __expf(a.x - mx); a.y = __expf(a.y - mx);
    a.z = __expf(a.z - mx); a.w = __expf(a.w - mx);
    c.x = __expf(c.x - mx); c.y = __expf(c.y - mx);
    c.z = __expf(c.z - mx); c.w = __expf(c.w - mx);
    float sum = (a.x + a.y + a.z + a.w) + (c.x + c.y + c.z + c.w);
    red[tid] = sum; __syncthreads();
    #pragma unroll
    for (int s = 128; s > 0; s >>= 1) {
        if (tid < s) red[tid] += red[tid + s];
        __syncthreads();
    }
    float inv = 1.0f / red[0];
    a.x *= inv; a.y *= inv; a.z *= inv; a.w *= inv;
    c.x *= inv; c.y *= inv; c.z *= inv; c.w *= inv;
    p[tid] = a;
    p[tid + 256] = c;
}

__global__ void ctx_kernel(const float* __restrict__ probs,
                           const float* __restrict__ v,
                           float* __restrict__ ctx) {
    __shared__ __align__(16) float Ps[32][128];
    __shared__ __align__(16) float Vs[32][64];
    const int z = blockIdx.z;
    const int b = z / HH;
    const int h = z % HH;
    const float* P = probs + (size_t)(b * HH + h) * LL * SS;
    const int bm = blockIdx.y * 128;
    const int tid = threadIdx.x;
    const int tr  = (tid >> 4) * 8;
    const int tc  = (tid & 15) * 4;

    float acc[8][4];
    #pragma unroll
    for (int i = 0; i < 8; i++)
        #pragma unroll
        for (int j = 0; j < 4; j++) acc[i][j] = 0.0f;

    const int prow = tid >> 3;
    const int pk   = (tid & 7) * 4;
    const int vrow = tid >> 4;
    const int vj   = (tid & 15) * 4;

    for (int k0 = 0; k0 < SS; k0 += 32) {
        #pragma unroll
        for (int i = 0; i < 4; i++) {
            int r = prow + i * 32;
            float4 a = *(const float4*)(P + (size_t)(bm + r) * SS + k0 + pk);
            Ps[pk + 0][r] = a.x; Ps[pk + 1][r] = a.y;
            Ps[pk + 2][r] = a.z; Ps[pk + 3][r] = a.w;
        }
        #pragma unroll
        for (int i = 0; i < 2; i++) {
            int r = vrow + i * 16;
            float4 w = *(const float4*)(v + (size_t)(b * SS + k0 + r) * DV + h * HD + vj);
            *(float4*)&Vs[r][vj] = w;
        }
        __syncthreads();
        #pragma unroll
        for (int k = 0; k < 32; k++) {
            float af[8], bf[4];
            #pragma unroll
            for (int i = 0; i < 8; i++) af[i] = Ps[k][tr + i];
            #pragma unroll
            for (int j = 0; j < 4; j++) bf[j] = Vs[k][tc + j];
            #pragma unroll
            for (int i = 0; i < 8; i++)
                #pragma unroll
                for (int j = 0; j < 4; j++) acc[i][j] += af[i] * bf[j];
        }
        __syncthreads();
    }
    #pragma unroll
    for (int i = 0; i < 8; i++) {
        size_t base = (size_t)(b * LL + bm + tr + i) * DV + h * HD;
        #pragma unroll
        for (int j = 0; j < 4; j++) ctx[base + tc + j] = acc[i][j];
    }
}

// ---------------------------------------------------------------------------
extern "C" void kernel_launch(void* const* d_in, const int* in_sizes, int n_in,
                              void* d_out, int out_size) {
    const float* queries = (const float*)d_in[0];
    const float* keys    = (const float*)d_in[1];
    const float* values  = (const float*)d_in[2];
    const float* Wq      = (const float*)d_in[4];
    const float* Wk      = (const float*)d_in[5];
    const float* Wv      = (const float*)d_in[6];
    const float* bv      = (const float*)d_in[7];
    const float* Wcb     = (const float*)d_in[8];
    const float* mixing  = (const float*)d_in[9];
    const float* Wd      = (const float*)d_in[10];
    const float* bd      = (const float*)d_in[11];

    float* out = (float*)d_out;

    void *pq, *pk, *pv, *pcb, *pctx, *pprobs;
    cudaGetSymbolAddress(&pq,   g_q);
    cudaGetSymbolAddress(&pk,   g_k);
    cudaGetSymbolAddress(&pv,   g_v);
    cudaGetSymbolAddress(&pcb,  g_cb);
    cudaGetSymbolAddress(&pctx, g_ctx);
    cudaGetSymbolAddress(&pprobs, g_probs);

    float* probs;
    if ((long)out_size >= OUT_ELEMS + PROB_ELEMS) probs = out + OUT_ELEMS;
    else                                           probs = (float*)pprobs;

    const int M = BB * LL;

    cb_kernel<<<BB * SS, 256>>>(keys, Wcb, (float*)pcb);

    dim3 gproj(DOUT / 128, M / 128);
    gemm_abT_kernel<false><<<gproj, 256>>>(queries, Wq, nullptr, (float*)pq, M, DK,  DIN);
    gemm_abT_kernel<false><<<gproj, 256>>>(keys,    Wk, nullptr, (float*)pk, M, DK,  DIN);
    gemm_abT_kernel<true ><<<gproj, 256>>>(values,  Wv, bv,      (float*)pv, M, DV,  DIN);

    // tf32 mma.sync scores
    dim3 gsc(SS / 128, LL / 128, BB * HH);
    scores_mma_kernel<<<gsc, 256>>>((const float*)pq, (const float*)pk,
                                    mixing, (const float*)pcb, probs);

    softmax_kernel<<<BB * HH * LL, 256>>>(probs);

    dim3 gctx(1, LL / 128, BB * HH);
    ctx_kernel<<<gctx, 256>>>(probs, (const float*)pv, (float*)pctx);

    gemm_abT_kernel<true><<<gproj, 256>>>((const float*)pctx, Wd, bd, out, M, DOUT, DV);
}

// round 5
// speedup vs baseline: 2.7440x; 1.4164x over previous
#include <cuda_runtime.h>
#include <cuda_bf16.h>
#include <cstdint>

// Problem constants
#define BB   2
#define LL   2048
#define SS   2048
#define DIN  512
#define DK   512
#define DV   512
#define DOUT 512
#define HH   8
#define HD   64

#define OUT_ELEMS  ((long)BB * LL * DOUT)
#define PROB_ELEMS ((long)BB * HH * (long)LL * (long)SS)

// Scratch (device globals — no runtime allocation allowed)
__device__ float g_q  [BB * LL * DK];
__device__ float g_k  [BB * SS * DK];
__device__ float g_v  [BB * SS * DV];
__device__ float g_cb [BB * HH * SS];
__device__ float g_ctx[BB * LL * DV];
__device__ float g_probs[BB * HH * (long)LL * SS];

// ---------------------------------------------------------------------------
// tf32 helpers (harness targets plain sm_103 — no tcgen05; mma.sync is the
// tensor path)
// ---------------------------------------------------------------------------
__device__ __forceinline__ float f2tf32(float v) {
    uint32_t r;
    asm("cvt.rna.tf32.f32 %0, %1;" : "=r"(r) : "f"(v));
    return __uint_as_float(r);
}

__device__ __forceinline__ void mma_tf32(float& c0, float& c1, float& c2, float& c3,
                                         float a0, float a1, float a2, float a3,
                                         float b0, float b1) {
    asm volatile(
        "mma.sync.aligned.m16n8k8.row.col.f32.tf32.tf32.f32 "
        "{%0,%1,%2,%3}, {%4,%5,%6,%7}, {%8,%9}, {%0,%1,%2,%3};"
        : "+f"(c0), "+f"(c1), "+f"(c2), "+f"(c3)
        : "r"(__float_as_uint(a0)), "r"(__float_as_uint(a1)),
          "r"(__float_as_uint(a2)), "r"(__float_as_uint(a3)),
          "r"(__float_as_uint(b0)), "r"(__float_as_uint(b1)));
}

#define SKP 20   // smem row stride (floats): conflict-free fragment reads

// ---------------------------------------------------------------------------
// Generic tf32 mma GEMM: C[M,N] = A[M,K] * W[N,K]^T (+ bias[n])
// CTA tile 128x128, BK=16 double-buffered, 8 warps (2m x 4n), warp 64x32.
// ---------------------------------------------------------------------------
template <bool HAS_BIAS>
__global__ __launch_bounds__(256, 2)
void gemm_mma_kernel(const float* __restrict__ A,
                     const float* __restrict__ W,
                     const float* __restrict__ bias,
                     float* __restrict__ C,
                     int M, int N, int K) {
    __shared__ float As[2][128][SKP];
    __shared__ float Bs[2][128][SKP];
    __shared__ float bias_s[128];

    const int tid  = threadIdx.x;
    const int wid  = tid >> 5;
    const int lane = tid & 31;
    const int warp_m = wid >> 2;
    const int warp_n = wid & 3;

    const int bm = blockIdx.y * 128;
    const int bn = blockIdx.x * 128;

    const float* Ag = A + (size_t)bm * K;
    const float* Wg = W + (size_t)bn * K;

    if (HAS_BIAS && tid < 128) bias_s[tid] = bias[bn + tid];
    __syncthreads();

    const int gr = tid >> 2;
    const int gc = (tid & 3) * 4;

    float acc[4][4][4];
    #pragma unroll
    for (int i = 0; i < 4; i++)
        #pragma unroll
        for (int j = 0; j < 4; j++)
            #pragma unroll
            for (int t = 0; t < 4; t++) acc[i][j][t] = 0.0f;

    float4 pa[2], pb[2];

    #pragma unroll
    for (int i = 0; i < 2; i++) {
        pa[i] = *(const float4*)(Ag + (size_t)(gr + i * 64) * K + gc);
        pb[i] = *(const float4*)(Wg + (size_t)(gr + i * 64) * K + gc);
    }
    #pragma unroll
    for (int i = 0; i < 2; i++) {
        int r = gr + i * 64;
        float4 ta = make_float4(f2tf32(pa[i].x), f2tf32(pa[i].y), f2tf32(pa[i].z), f2tf32(pa[i].w));
        float4 tb = make_float4(f2tf32(pb[i].x), f2tf32(pb[i].y), f2tf32(pb[i].z), f2tf32(pb[i].w));
        *(float4*)&As[0][r][gc] = ta;
        *(float4*)&Bs[0][r][gc] = tb;
    }
    __syncthreads();

    const int NC = K / 16;
    for (int c = 0; c < NC; c++) {
        if (c + 1 < NC) {
            int kc = (c + 1) * 16;
            #pragma unroll
            for (int i = 0; i < 2; i++) {
                pa[i] = *(const float4*)(Ag + (size_t)(gr + i * 64) * K + kc + gc);
                pb[i] = *(const float4*)(Wg + (size_t)(gr + i * 64) * K + kc + gc);
            }
        }

        const int st = c & 1;
        #pragma unroll
        for (int kk = 0; kk < 2; kk++) {
            const int k0 = kk * 8;
            const int ar = lane >> 2;
            const int ac = lane & 3;
            float a0[4], a1[4], a2[4], a3[4];
            #pragma unroll
            for (int i = 0; i < 4; i++) {
                int m = warp_m * 64 + i * 16;
                a0[i] = As[st][m + ar    ][k0 + ac    ];
                a1[i] = As[st][m + ar + 8][k0 + ac    ];
                a2[i] = As[st][m + ar    ][k0 + ac + 4];
                a3[i] = As[st][m + ar + 8][k0 + ac + 4];
            }
            float b0[4], b1[4];
            #pragma unroll
            for (int j = 0; j < 4; j++) {
                int n = warp_n * 32 + j * 8 + (lane >> 2);
                b0[j] = Bs[st][n][k0 + ac    ];
                b1[j] = Bs[st][n][k0 + ac + 4];
            }
            #pragma unroll
            for (int i = 0; i < 4; i++)
                #pragma unroll
                for (int j = 0; j < 4; j++)
                    mma_tf32(acc[i][j][0], acc[i][j][1], acc[i][j][2], acc[i][j][3],
                             a0[i], a1[i], a2[i], a3[i], b0[j], b1[j]);
        }

        if (c + 1 < NC) {
            __syncthreads();
            const int ns = (c + 1) & 1;
            #pragma unroll
            for (int i = 0; i < 2; i++) {
                int r = gr + i * 64;
                float4 ta = make_float4(f2tf32(pa[i].x), f2tf32(pa[i].y), f2tf32(pa[i].z), f2tf32(pa[i].w));
                float4 tb = make_float4(f2tf32(pb[i].x), f2tf32(pb[i].y), f2tf32(pb[i].z), f2tf32(pb[i].w));
                *(float4*)&As[ns][r][gc] = ta;
                *(float4*)&Bs[ns][r][gc] = tb;
            }
            __syncthreads();
        }
    }

    #pragma unroll
    for (int i = 0; i < 4; i++) {
        int row = bm + warp_m * 64 + i * 16 + (lane >> 2);
        #pragma unroll
        for (int j = 0; j < 4; j++) {
            int col = warp_n * 32 + j * 8 + (lane & 3) * 2;
            float bb0 = HAS_BIAS ? bias_s[col]     : 0.0f;
            float bb1 = HAS_BIAS ? bias_s[col + 1] : 0.0f;
            float2 v0, v1;
            v0.x = acc[i][j][0] + bb0; v0.y = acc[i][j][1] + bb1;
            v1.x = acc[i][j][2] + bb0; v1.y = acc[i][j][3] + bb1;
            *(float2*)(C + (size_t)row * N + bn + col) = v0;
            *(float2*)(C + (size_t)(row + 8) * N + bn + col) = v1;
        }
    }
}

// ---------------------------------------------------------------------------
// Scores via tf32 mma (unchanged from R4 — passing):
// P[b,h,l,s] = (sum_e q[b,l,e]*mix[h,e]*k[b,s,e] + cb[b,h,s]) * 0.125
// ---------------------------------------------------------------------------
__global__ __launch_bounds__(256, 2)
void scores_mma_kernel(const float* __restrict__ q,
                       const float* __restrict__ kmat,
                       const float* __restrict__ mixing,
                       const float* __restrict__ cb,
                       float* __restrict__ probs) {
    __shared__ float As[2][128][SKP];
    __shared__ float Bs[2][128][SKP];
    __shared__ float mix_s[DK];
    __shared__ float cb_s[128];

    const int tid  = threadIdx.x;
    const int wid  = tid >> 5;
    const int lane = tid & 31;
    const int warp_m = wid >> 2;
    const int warp_n = wid & 3;

    const int z  = blockIdx.z;
    const int b  = z >> 3;
    const int h  = z & 7;
    const int bm = blockIdx.y * 128;
    const int bn = blockIdx.x * 128;

    const float* Aq = q    + (size_t)b * LL * DK + (size_t)bm * DK;
    const float* Bk = kmat + (size_t)b * SS * DK + (size_t)bn * DK;

    for (int i = tid; i < DK; i += 256) mix_s[i] = mixing[h * DK + i];
    if (tid < 128) cb_s[tid] = cb[(size_t)(b * HH + h) * SS + bn + tid];
    __syncthreads();

    const int gr = tid >> 2;
    const int gc = (tid & 3) * 4;

    float acc[4][4][4];
    #pragma unroll
    for (int i = 0; i < 4; i++)
        #pragma unroll
        for (int j = 0; j < 4; j++)
            #pragma unroll
            for (int t = 0; t < 4; t++) acc[i][j][t] = 0.0f;

    float4 pa[2], pb[2];

    #pragma unroll
    for (int i = 0; i < 2; i++) {
        pa[i] = *(const float4*)(Aq + (size_t)(gr + i * 64) * DK + gc);
        pb[i] = *(const float4*)(Bk + (size_t)(gr + i * 64) * DK + gc);
    }
    #pragma unroll
    for (int i = 0; i < 2; i++) {
        int r = gr + i * 64;
        As[0][r][gc + 0] = f2tf32(pa[i].x);
        As[0][r][gc + 1] = f2tf32(pa[i].y);
        As[0][r][gc + 2] = f2tf32(pa[i].z);
        As[0][r][gc + 3] = f2tf32(pa[i].w);
        Bs[0][r][gc + 0] = f2tf32(pb[i].x * mix_s[gc + 0]);
        Bs[0][r][gc + 1] = f2tf32(pb[i].y * mix_s[gc + 1]);
        Bs[0][r][gc + 2] = f2tf32(pb[i].z * mix_s[gc + 2]);
        Bs[0][r][gc + 3] = f2tf32(pb[i].w * mix_s[gc + 3]);
    }
    __syncthreads();

    const int NC = DK / 16;
    for (int c = 0; c < NC; c++) {
        if (c + 1 < NC) {
            int kc = (c + 1) * 16;
            #pragma unroll
            for (int i = 0; i < 2; i++) {
                pa[i] = *(const float4*)(Aq + (size_t)(gr + i * 64) * DK + kc + gc);
                pb[i] = *(const float4*)(Bk + (size_t)(gr + i * 64) * DK + kc + gc);
            }
        }

        const int st = c & 1;
        #pragma unroll
        for (int kk = 0; kk < 2; kk++) {
            const int k0 = kk * 8;
            const int ar = lane >> 2;
            const int ac = lane & 3;
            float a0[4], a1[4], a2[4], a3[4];
            #pragma unroll
            for (int i = 0; i < 4; i++) {
                int m = warp_m * 64 + i * 16;
                a0[i] = As[st][m + ar    ][k0 + ac    ];
                a1[i] = As[st][m + ar + 8][k0 + ac    ];
                a2[i] = As[st][m + ar    ][k0 + ac + 4];
                a3[i] = As[st][m + ar + 8][k0 + ac + 4];
            }
            float b0[4], b1[4];
            #pragma unroll
            for (int j = 0; j < 4; j++) {
                int n = warp_n * 32 + j * 8 + (lane >> 2);
                b0[j] = Bs[st][n][k0 + ac    ];
                b1[j] = Bs[st][n][k0 + ac + 4];
            }
            #pragma unroll
            for (int i = 0; i < 4; i++)
                #pragma unroll
                for (int j = 0; j < 4; j++)
                    mma_tf32(acc[i][j][0], acc[i][j][1], acc[i][j][2], acc[i][j][3],
                             a0[i], a1[i], a2[i], a3[i], b0[j], b1[j]);
        }

        if (c + 1 < NC) {
            __syncthreads();
            const int ns = (c + 1) & 1;
            const int kc = (c + 1) * 16;
            #pragma unroll
            for (int i = 0; i < 2; i++) {
                int r = gr + i * 64;
                As[ns][r][gc + 0] = f2tf32(pa[i].x);
                As[ns][r][gc + 1] = f2tf32(pa[i].y);
                As[ns][r][gc + 2] = f2tf32(pa[i].z);
                As[ns][r][gc + 3] = f2tf32(pa[i].w);
                Bs[ns][r][gc + 0] = f2tf32(pb[i].x * mix_s[kc + gc + 0]);
                Bs[ns][r][gc + 1] = f2tf32(pb[i].y * mix_s[kc + gc + 1]);
                Bs[ns][r][gc + 2] = f2tf32(pb[i].z * mix_s[kc + gc + 2]);
                Bs[ns][r][gc + 3] = f2tf32(pb[i].w * mix_s[kc + gc + 3]);
            }
            __syncthreads();
        }
    }

    const size_t rowbase = (size_t)(b * HH + h) * LL;
    #pragma unroll
    for (int i = 0; i < 4; i++) {
        int row = bm + warp_m * 64 + i * 16 + (lane >> 2);
        #pragma unroll
        for (int j = 0; j < 4; j++) {
            int col = warp_n * 32 + j * 8 + (lane & 3) * 2;
            float cb0 = cb_s[col], cb1 = cb_s[col + 1];
            float2 v0, v1;
            v0.x = (acc[i][j][0] + cb0) * 0.125f;
            v0.y = (acc[i][j][1] + cb1) * 0.125f;
            v1.x = (acc[i][j][2] + cb0) * 0.125f;
            v1.y = (acc[i][j][3] + cb1) * 0.125f;
            *(float2*)(probs + (rowbase + row    ) * SS + bn + col) = v0;
            *(float2*)(probs + (rowbase + row + 8) * SS + bn + col) = v1;
        }
    }
}

// ---------------------------------------------------------------------------
// ctx via tf32 mma: per (b,h)  C[2048x64] = P[2048x2048] @ Vh[2048x64]
// CTA tile 128x64, BK=16 double-buffered, 8 warps (2m x 4n), warp 64x16.
// V kept K-major in smem (stride 72 -> conflict-free B-frag reads).
// grid = (L/128, B*H), 256 threads.
// ---------------------------------------------------------------------------
__global__ __launch_bounds__(256, 2)
void ctx_mma_kernel(const float* __restrict__ probs,
                    const float* __restrict__ v,
                    float* __restrict__ ctx) {
    __shared__ float Ps[2][128][SKP];   // [row l][k s]
    __shared__ float Vs[2][16][72];     // [k s][n dv]

    const int tid  = threadIdx.x;
    const int wid  = tid >> 5;
    const int lane = tid & 31;
    const int warp_m = wid >> 2;   // 0..1 (64 rows each)
    const int warp_n = wid & 3;    // 0..3 (16 cols each)

    const int z  = blockIdx.y;     // b*H + h
    const int b  = z >> 3;
    const int h  = z & 7;
    const int bm = blockIdx.x * 128;

    const float* P = probs + ((size_t)z * LL + bm) * SS;
    const float* V = v + (size_t)b * SS * DV + h * HD;

    // P loads: 512 float4/chunk, 2 per thread
    const int pr = tid >> 2;          // 0..63 (+64)
    const int pc = (tid & 3) * 4;     // 0..12
    // V loads: 256 float4/chunk, 1 per thread
    const int vs = tid >> 4;          // 0..15
    const int vd = (tid & 15) * 4;    // 0..60

    float acc[4][2][4];
    #pragma unroll
    for (int i = 0; i < 4; i++)
        #pragma unroll
        for (int j = 0; j < 2; j++)
            #pragma unroll
            for (int t = 0; t < 4; t++) acc[i][j][t] = 0.0f;

    float4 pp[2], pv;

    #pragma unroll
    for (int i = 0; i < 2; i++)
        pp[i] = *(const float4*)(P + (size_t)(pr + i * 64) * SS + pc);
    pv = *(const float4*)(V + (size_t)vs * DV + vd);

    #pragma unroll
    for (int i = 0; i < 2; i++) {
        int r = pr + i * 64;
        float4 t = make_float4(f2tf32(pp[i].x), f2tf32(pp[i].y), f2tf32(pp[i].z), f2tf32(pp[i].w));
        *(float4*)&Ps[0][r][pc] = t;
    }
    {
        float4 t = make_float4(f2tf32(pv.x), f2tf32(pv.y), f2tf32(pv.z), f2tf32(pv.w));
        *(float4*)&Vs[0][vs][vd] = t;
    }
    __syncthreads();

    const int NC = SS / 16;   // 128 chunks
    for (int c = 0; c < NC; c++) {
        if (c + 1 < NC) {
            int kc = (c + 1) * 16;
            #pragma unroll
            for (int i = 0; i < 2; i++)
                pp[i] = *(const float4*)(P + (size_t)(pr + i * 64) * SS + kc + pc);
            pv = *(const float4*)(V + (size_t)(kc + vs) * DV + vd);
        }

        const int st = c & 1;
        #pragma unroll
        for (int kk = 0; kk < 2; kk++) {
            const int k0 = kk * 8;
            const int ar = lane >> 2;
            const int ac = lane & 3;
            float a0[4], a1[4], a2[4], a3[4];
            #pragma unroll
            for (int i = 0; i < 4; i++) {
                int m = warp_m * 64 + i * 16;
                a0[i] = Ps[st][m + ar    ][k0 + ac    ];
                a1[i] = Ps[st][m + ar + 8][k0 + ac    ];
                a2[i] = Ps[st][m + ar    ][k0 + ac + 4];
                a3[i] = Ps[st][m + ar + 8][k0 + ac + 4];
            }
            float b0[2], b1[2];
            #pragma unroll
            for (int j = 0; j < 2; j++) {
                int n = warp_n * 16 + j * 8 + (lane >> 2);
                b0[j] = Vs[st][k0 + ac    ][n];
                b1[j] = Vs[st][k0 + ac + 4][n];
            }
            #pragma unroll
            for (int i = 0; i < 4; i++)
                #pragma unroll
                for (int j = 0; j < 2; j++)
                    mma_tf32(acc[i][j][0], acc[i][j][1], acc[i][j][2], acc[i][j][3],
                             a0[i], a1[i], a2[i], a3[i], b0[j], b1[j]);
        }

        if (c + 1 < NC) {
            __syncthreads();
            const int ns = (c + 1) & 1;
            #pragma unroll
            for (int i = 0; i < 2; i++) {
                int r = pr + i * 64;
                float4 t = make_float4(f2tf32(pp[i].x), f2tf32(pp[i].y), f2tf32(pp[i].z), f2tf32(pp[i].w));
                *(float4*)&Ps[ns][r][pc] = t;
            }
            {
                float4 t = make_float4(f2tf32(pv.x), f2tf32(pv.y), f2tf32(pv.z), f2tf32(pv.w));
                *(float4*)&Vs[ns][vs][vd] = t;
            }
            __syncthreads();
        }
    }

    #pragma unroll
    for (int i = 0; i < 4; i++) {
        int row = bm + warp_m * 64 + i * 16 + (lane >> 2);
        #pragma unroll
        for (int j = 0; j < 2; j++) {
            int col = warp_n * 16 + j * 8 + (lane & 3) * 2;
            float2 v0, v1;
            v0.x = acc[i][j][0]; v0.y = acc[i][j][1];
            v1.x = acc[i][j][2]; v1.y = acc[i][j][3];
            *(float2*)(ctx + (size_t)(b * LL + row) * DV + h * HD + col) = v0;
            *(float2*)(ctx + (size_t)(b * LL + row + 8) * DV + h * HD + col) = v1;
        }
    }
}

// ---------------------------------------------------------------------------
// cb + softmax (unchanged)
// ---------------------------------------------------------------------------
__global__ void cb_kernel(const float* __restrict__ keys,
                          const float* __restrict__ Wcb,
                          float* __restrict__ cb) {
    const int bs = blockIdx.x;
    const int b  = bs / SS;
    const int s  = bs % SS;
    __shared__ float krow[DIN];
    const int tid = threadIdx.x;
    for (int i = tid; i < DIN; i += 256) krow[i] = keys[(size_t)bs * DIN + i];
    __syncthreads();
    const int w    = tid >> 5;
    const int lane = tid & 31;
    float sum = 0.0f;
    #pragma unroll 4
    for (int i = lane; i < DIN; i += 32) sum += krow[i] * Wcb[w * DIN + i];
    #pragma unroll
    for (int o = 16; o > 0; o >>= 1) sum += __shfl_down_sync(0xffffffffu, sum, o);
    if (lane == 0) cb[(size_t)(b * HH + w) * SS + s] = sum;
}

__global__ void softmax_kernel(float* __restrict__ probs) {
    float4* p = (float4*)(probs + (size_t)blockIdx.x * SS);
    const int tid = threadIdx.x;
    float4 a = p[tid];
    float4 c = p[tid + 256];
    float mx = fmaxf(fmaxf(fmaxf(a.x, a.y), fmaxf(a.z, a.w)),
                     fmaxf(fmaxf(c.x, c.y), fmaxf(c.z, c.w)));
    __shared__ float red[256];
    red[tid] = mx; __syncthreads();
    #pragma unroll
    for (int s = 128; s > 0; s >>= 1) {
        if (tid < s) red[tid] = fmaxf(red[tid], red[tid + s]);
        __syncthreads();
    }
    mx = red[0];
    __syncthreads();
    a.x = __expf(a.x - mx); a.y = __expf(a.y - mx);
    a.z = __expf(a.z - mx); a.w = __expf(a.w - mx);
    c.x = __expf(c.x - mx); c.y = __expf(c.y - mx);
    c.z = __expf(c.z - mx); c.w = __expf(c.w - mx);
    float sum = (a.x + a.y + a.z + a.w) + (c.x + c.y + c.z + c.w);
    red[tid] = sum; __syncthreads();
    #pragma unroll
    for (int s = 128; s > 0; s >>= 1) {
        if (tid < s) red[tid] += red[tid + s];
        __syncthreads();
    }
    float inv = 1.0f / red[0];
    a.x *= inv; a.y *= inv; a.z *= inv; a.w *= inv;
    c.x *= inv; c.y *= inv; c.z *= inv; c.w *= inv;
    p[tid] = a;
    p[tid + 256] = c;
}

// ---------------------------------------------------------------------------
extern "C" void kernel_launch(void* const* d_in, const int* in_sizes, int n_in,
                              void* d_out, int out_size) {
    const float* queries = (const float*)d_in[0];
    const float* keys    = (const float*)d_in[1];
    const float* values  = (const float*)d_in[2];
    const float* Wq      = (const float*)d_in[4];
    const float* Wk      = (const float*)d_in[5];
    const float* Wv      = (const float*)d_in[6];
    const float* bv      = (const float*)d_in[7];
    const float* Wcb     = (const float*)d_in[8];
    const float* mixing  = (const float*)d_in[9];
    const float* Wd      = (const float*)d_in[10];
    const float* bd      = (const float*)d_in[11];

    float* out = (float*)d_out;

    void *pq, *pk, *pv, *pcb, *pctx, *pprobs;
    cudaGetSymbolAddress(&pq,   g_q);
    cudaGetSymbolAddress(&pk,   g_k);
    cudaGetSymbolAddress(&pv,   g_v);
    cudaGetSymbolAddress(&pcb,  g_cb);
    cudaGetSymbolAddress(&pctx, g_ctx);
    cudaGetSymbolAddress(&pprobs, g_probs);

    float* probs;
    if ((long)out_size >= OUT_ELEMS + PROB_ELEMS) probs = out + OUT_ELEMS;
    else                                           probs = (float*)pprobs;

    const int M = BB * LL;

    cb_kernel<<<BB * SS, 256>>>(keys, Wcb, (float*)pcb);

    dim3 gproj(DOUT / 128, M / 128);
    gemm_mma_kernel<false><<<gproj, 256>>>(queries, Wq, nullptr, (float*)pq, M, DK,  DIN);
    gemm_mma_kernel<false><<<gproj, 256>>>(keys,    Wk, nullptr, (float*)pk, M, DK,  DIN);
    gemm_mma_kernel<true ><<<gproj, 256>>>(values,  Wv, bv,      (float*)pv, M, DV,  DIN);

    dim3 gsc(SS / 128, LL / 128, BB * HH);
    scores_mma_kernel<<<gsc, 256>>>((const float*)pq, (const float*)pk,
                                    mixing, (const float*)pcb, probs);

    softmax_kernel<<<BB * HH * LL, 256>>>(probs);

    dim3 gctx(LL / 128, BB * HH);
    ctx_mma_kernel<<<gctx, 256>>>(probs, (const float*)pv, (float*)pctx);

    gemm_mma_kernel<true><<<gproj, 256>>>((const float*)pctx, Wd, bd, out, M, DOUT, DV);
}